// round 12
// baseline (speedup 1.0000x reference)
#include <cuda_runtime.h>
#include <cuda_bf16.h>

// Problem constants (fixed by setup_inputs): B=8, N=128, T=1024, K=3
#define BB    8
#define NN    128
#define TT    1024
#define NWARP 16            // 512 threads, 2 points per thread, ITERS = 1

__global__ __launch_bounds__(512, 4) void fused_arc_conv_kernel(
    const float* __restrict__ k,
    const float* __restrict__ leak,
    const float* __restrict__ alpha,
    const float* __restrict__ beta,
    float* __restrict__ out)
{
    // warp-boundary exchange only
    __shared__ float2 sFirst[NWARP];   // (c0, d) of each warp's first point (lane 0, point a)
    __shared__ float2 sLast[NWARP];    // (c0, d) of each warp's last point  (lane 31, point b)

    const int row = blockIdx.x;          // 0 .. B*B*N-1, layout (i,j,n)
    const int n   = row & (NN - 1);
    const int ij  = row >> 7;
    const int j   = ij & (BB - 1);
    const int i   = ij >> 3;

    const float a  = fmaxf(leak[0], 0.0f);
    const float w0 = fmaxf(alpha[0], 0.0f);
    const float w1 = fmaxf(alpha[1], 0.0f);
    const float w2 = fmaxf(alpha[2], 0.0f);
    const float bv = fmaxf(beta[0], 0.0f);

    const float PIf    = 3.14159265358979323846f;
    const float one_m  = (1.0f - a) * (1.0f - a);
    const float coef   = 1.0f + a * a;
    const float inv2pi = 1.0f / (2.0f * PIf);
    const float RL     = 1.0f - 1e-6f;
    const float EPS    = 1e-12f;
    const bool  fast   = (one_m == 0.0f);   // leak == 1 -> halfcoef == 1

    const float2* __restrict__ krow = reinterpret_cast<const float2*>(k) + (size_t)row * TT;
    float2* __restrict__ orow       = reinterpret_cast<float2*>(out)     + (size_t)row * TT;
    // diagonal rows (i,i,0,:) / (j,j,0,:) carrying variance; L1/L2-resident (64KB total)
    const float2* __restrict__ kdi = reinterpret_cast<const float2*>(k) + (size_t)(i * BB + i) * NN * TT;
    const float2* __restrict__ kdj = reinterpret_cast<const float2*>(k) + (size_t)(j * BB + j) * NN * TT;

    const int tid  = threadIdx.x;
    const int warp = tid >> 5;
    const int lane = tid & 31;
    const unsigned FULL = 0xffffffffu;

    // ---------- phase 1: pairwise pointwise (registers only) ----------
    const int p = tid * 2;                                         // even
    const float4 kv4 = *reinterpret_cast<const float4*>(krow + p); // (gp0,ntk0,gp1,ntk1)
    const float4 vx4 = *reinterpret_cast<const float4*>(kdi + p);  // (vx0, -, vx1, -)
    const int ty0 = n + p;
    const float vy0 = (ty0 < TT)     ? kdj[ty0].x     : 0.0f;
    const float vy1 = (ty0 + 1 < TT) ? kdj[ty0 + 1].x : 0.0f;

    const float sxy0 = sqrtf(fmaxf(vx4.x, 0.0f) * fmaxf(vy0, 0.0f));
    const float sxy1 = sqrtf(fmaxf(vx4.z, 0.0f) * fmaxf(vy1, 0.0f));

    float c0a, c0b, da, db;
    if (fast) {
        const float l0 = RL * sxy0;
        const float l1 = RL * sxy1;
        c0a = fminf(fmaxf(kv4.x, -l0), l0);  da = kv4.y;
        c0b = fminf(fmaxf(kv4.z, -l1), l1);  db = kv4.w;
    } else {
        const float dn0 = fmaxf(sxy0, EPS);
        float rho0 = fminf(fmaxf(kv4.x / dn0, -RL), RL);
        const float th0 = acosf(rho0);
        const float sn0 = sqrtf(fmaxf(1.0f - rho0 * rho0, 0.0f));
        const float tp0 = coef * PIf - one_m * th0;
        c0a = sxy0 * inv2pi * (one_m * sn0 + rho0 * tp0);
        da  = tp0 * inv2pi * kv4.y;

        const float dn1 = fmaxf(sxy1, EPS);
        float rho1 = fminf(fmaxf(kv4.z / dn1, -RL), RL);
        const float th1 = acosf(rho1);
        const float sn1 = sqrtf(fmaxf(1.0f - rho1 * rho1, 0.0f));
        const float tp1 = coef * PIf - one_m * th1;
        c0b = sxy1 * inv2pi * (one_m * sn1 + rho1 * tp1);
        db  = tp1 * inv2pi * kv4.w;
    }

    if (lane == 0)  sFirst[warp] = make_float2(c0a, da);
    if (lane == 31) sLast[warp]  = make_float2(c0b, db);
    __syncthreads();

    // ---------- phase 2: 3-tap conv; halos via shfl, warp boundaries via tiny smem ----------
    float Lc = __shfl_up_sync(FULL, c0b, 1);    // point p-1 c0
    float Ld = __shfl_up_sync(FULL, db, 1);     // point p-1 d
    float Rc = __shfl_down_sync(FULL, c0a, 1);  // point p+2 c0
    float Rd = __shfl_down_sync(FULL, da, 1);   // point p+2 d

    if (lane == 0) {
        float2 v = (warp > 0) ? sLast[warp - 1] : make_float2(0.0f, 0.0f);
        Lc = v.x; Ld = v.y;
    }
    if (lane == 31) {
        float2 v = (warp < NWARP - 1) ? sFirst[warp + 1] : make_float2(0.0f, 0.0f);
        Rc = v.x; Rd = v.y;
    }

    const float kg0 = w0 * Lc  + w1 * c0a + w2 * c0b + bv;
    const float kg1 = w0 * c0a + w1 * c0b + w2 * Rc  + bv;
    const float kn0 = w0 * Ld  + w1 * da  + w2 * db  + kg0;
    const float kn1 = w0 * da  + w1 * db  + w2 * Rd  + kg1;

    __stcs(reinterpret_cast<float4*>(orow + p), make_float4(kg0, kn0, kg1, kn1));
}

extern "C" void kernel_launch(void* const* d_in, const int* in_sizes, int n_in,
                              void* d_out, int out_size) {
    const float* k     = (const float*)d_in[0];
    const float* leak  = (const float*)d_in[1];
    const float* alpha = (const float*)d_in[2];
    const float* beta  = (const float*)d_in[3];
    float* out = (float*)d_out;

    fused_arc_conv_kernel<<<BB * BB * NN, 512>>>(k, leak, alpha, beta, out);
}

// round 13
// speedup vs baseline: 1.0598x; 1.0598x over previous
#include <cuda_runtime.h>
#include <cuda_bf16.h>

// Problem constants (fixed by setup_inputs): B=8, N=128, T=1024, K=3
#define BB    8
#define NN    128
#define TT    1024
#define ITERS (TT / 512)   // 2 (each thread does a pair of points per iter)
#define NWARP 8
#define NSEG  (ITERS * NWARP)   // 16 segments of 64 points

__global__ __launch_bounds__(256, 8) void fused_arc_conv_kernel(
    const float* __restrict__ k,
    const float* __restrict__ leak,
    const float* __restrict__ alpha,
    const float* __restrict__ beta,
    float* __restrict__ out)
{
    // segment boundary exchange: segment g = it*NWARP + warp covers points [g*64, g*64+64)
    // sF[g+1] = (c0,d) of segment g's first point ; sL[g+1] = of its last point
    // index 0 and NSEG+1 are zero sentinels (left of point 0 / right of point TT-1)
    __shared__ float2 sF[NSEG + 2];
    __shared__ float2 sL[NSEG + 2];

    const int row = blockIdx.x;          // 0 .. B*B*N-1, layout (i,j,n)
    const int n   = row & (NN - 1);
    const int ij  = row >> 7;
    const int j   = ij & (BB - 1);
    const int i   = ij >> 3;

    const float a  = fmaxf(leak[0], 0.0f);
    const float w0 = fmaxf(alpha[0], 0.0f);
    const float w1 = fmaxf(alpha[1], 0.0f);
    const float w2 = fmaxf(alpha[2], 0.0f);
    const float bv = fmaxf(beta[0], 0.0f);

    const float PIf    = 3.14159265358979323846f;
    const float one_m  = (1.0f - a) * (1.0f - a);
    const float coef   = 1.0f + a * a;
    const float inv2pi = 1.0f / (2.0f * PIf);
    const float RL     = 1.0f - 1e-6f;
    const float EPS    = 1e-12f;
    const bool  fast   = (one_m == 0.0f);   // leak == 1 -> halfcoef == 1

    const float2* __restrict__ krow = reinterpret_cast<const float2*>(k) + (size_t)row * TT;
    float2* __restrict__ orow       = reinterpret_cast<float2*>(out)     + (size_t)row * TT;
    // diagonal rows (i,i,0,:) / (j,j,0,:) carrying variance; L1/L2-resident (64KB total)
    const float2* __restrict__ kdi = reinterpret_cast<const float2*>(k) + (size_t)(i * BB + i) * NN * TT;
    const float2* __restrict__ kdj = reinterpret_cast<const float2*>(k) + (size_t)(j * BB + j) * NN * TT;

    const int tid  = threadIdx.x;
    const int warp = tid >> 5;
    const int lane = tid & 31;
    const unsigned FULL = 0xffffffffu;

    // zero sentinels (4 independent threads)
    if (tid == 0) sF[0] = make_float2(0.0f, 0.0f);
    if (tid == 1) sL[0] = make_float2(0.0f, 0.0f);
    if (tid == 2) sF[NSEG + 1] = make_float2(0.0f, 0.0f);
    if (tid == 3) sL[NSEG + 1] = make_float2(0.0f, 0.0f);

    float c0a[ITERS], c0b[ITERS], da[ITERS], db[ITERS];

    // ---------- phase 1: pairwise pointwise (registers only) ----------
    #pragma unroll
    for (int it = 0; it < ITERS; ++it) {
        const int p = it * 512 + tid * 2;                 // even
        const float4 kv4 = *reinterpret_cast<const float4*>(krow + p); // (gp0,ntk0,gp1,ntk1)
        const float4 vx4 = *reinterpret_cast<const float4*>(kdi + p);  // (vx0, -, vx1, -)
        const int ty0 = n + p;
        const float vy0 = (ty0 < TT)     ? kdj[ty0].x     : 0.0f;
        const float vy1 = (ty0 + 1 < TT) ? kdj[ty0 + 1].x : 0.0f;

        const float sxy0 = sqrtf(fmaxf(vx4.x, 0.0f) * fmaxf(vy0, 0.0f));
        const float sxy1 = sqrtf(fmaxf(vx4.z, 0.0f) * fmaxf(vy1, 0.0f));

        float c00, d0, c01, d1;
        if (fast) {
            const float l0 = RL * sxy0;
            const float l1 = RL * sxy1;
            c00 = fminf(fmaxf(kv4.x, -l0), l0);  d0 = kv4.y;
            c01 = fminf(fmaxf(kv4.z, -l1), l1);  d1 = kv4.w;
        } else {
            const float dn0 = fmaxf(sxy0, EPS);
            float rho0 = fminf(fmaxf(kv4.x / dn0, -RL), RL);
            const float th0 = acosf(rho0);
            const float sn0 = sqrtf(fmaxf(1.0f - rho0 * rho0, 0.0f));
            const float tp0 = coef * PIf - one_m * th0;
            c00 = sxy0 * inv2pi * (one_m * sn0 + rho0 * tp0);
            d0  = tp0 * inv2pi * kv4.y;

            const float dn1 = fmaxf(sxy1, EPS);
            float rho1 = fminf(fmaxf(kv4.z / dn1, -RL), RL);
            const float th1 = acosf(rho1);
            const float sn1 = sqrtf(fmaxf(1.0f - rho1 * rho1, 0.0f));
            const float tp1 = coef * PIf - one_m * th1;
            c01 = sxy1 * inv2pi * (one_m * sn1 + rho1 * tp1);
            d1  = tp1 * inv2pi * kv4.w;
        }
        c0a[it] = c00; c0b[it] = c01;
        da[it]  = d0;  db[it]  = d1;
        const int g = it * NWARP + warp;
        if (lane == 0)  sF[g + 1] = make_float2(c00, d0);
        if (lane == 31) sL[g + 1] = make_float2(c01, d1);
    }
    __syncthreads();

    // ---------- phase 2: 3-tap conv; halos via shfl, segment boundaries via tiny smem ----------
    #pragma unroll
    for (int it = 0; it < ITERS; ++it) {
        const int p = it * 512 + tid * 2;
        const int g = it * NWARP + warp;

        float Lc = __shfl_up_sync(FULL, c0b[it], 1);    // point p-1 c0
        float Ld = __shfl_up_sync(FULL, db[it], 1);     // point p-1 d
        float Rc = __shfl_down_sync(FULL, c0a[it], 1);  // point p+2 c0
        float Rd = __shfl_down_sync(FULL, da[it], 1);   // point p+2 d

        if (lane == 0)  { const float2 v = sL[g];     Lc = v.x; Ld = v.y; }
        if (lane == 31) { const float2 v = sF[g + 2]; Rc = v.x; Rd = v.y; }

        const float kg0 = w0 * Lc      + w1 * c0a[it] + w2 * c0b[it] + bv;
        const float kg1 = w0 * c0a[it] + w1 * c0b[it] + w2 * Rc      + bv;
        const float kn0 = w0 * Ld      + w1 * da[it]  + w2 * db[it]  + kg0;
        const float kn1 = w0 * da[it]  + w1 * db[it]  + w2 * Rd      + kg1;

        __stcs(reinterpret_cast<float4*>(orow + p),
               make_float4(kg0, kn0, kg1, kn1));
    }
}

extern "C" void kernel_launch(void* const* d_in, const int* in_sizes, int n_in,
                              void* d_out, int out_size) {
    const float* k     = (const float*)d_in[0];
    const float* leak  = (const float*)d_in[1];
    const float* alpha = (const float*)d_in[2];
    const float* beta  = (const float*)d_in[3];
    float* out = (float*)d_out;

    fused_arc_conv_kernel<<<BB * BB * NN, 256>>>(k, leak, alpha, beta, out);
}

// round 14
// speedup vs baseline: 1.0703x; 1.0099x over previous
#include <cuda_runtime.h>
#include <cuda_bf16.h>

// Problem constants (fixed by setup_inputs): B=8, N=128, T=1024, K=3
#define BB    8
#define NN    128
#define TT    1024
#define VPAD  1152              // T + N - 1 = 1151 rounded up; tail zero-padded
#define ITERS (TT / 512)        // 2 (each thread does a pair of points per iter)

__device__ float g_stdv[BB * VPAD];

__global__ void prep_std_kernel(const float* __restrict__ k) {
    int idx = blockIdx.x * blockDim.x + threadIdx.x;
    if (idx >= BB * VPAD) return;
    int b = idx / VPAD;
    int t = idx - b * VPAD;
    float v = 0.0f;
    if (t < TT) {
        size_t off = ((size_t)(b * BB + b) * NN * TT + t) * 2;  // k_gp[b,b,0,t]
        v = k[off];
    }
    g_stdv[idx] = sqrtf(fmaxf(v, 0.0f));
}

struct Params {
    float one_m, coef, inv2pi;
    bool  fast;
};

// (c0, d) for point t of this row; used only for warp-boundary halo recompute.
__device__ __forceinline__ float2 point_cd(
    const float2* __restrict__ krow,
    const float* __restrict__ sx, const float* __restrict__ sy,
    int t, const Params& P)
{
    const float RL  = 1.0f - 1e-6f;
    const float EPS = 1e-12f;
    const float PIf = 3.14159265358979323846f;
    const float2 kv = krow[t];
    const float sxy = sx[t] * sy[t];
    float2 r;
    if (P.fast) {
        const float lim = RL * sxy;
        r.x = fminf(fmaxf(kv.x, -lim), lim);
        r.y = kv.y;
    } else {
        const float denom = fmaxf(sxy, EPS);
        float rho = fminf(fmaxf(kv.x / denom, -RL), RL);
        const float theta = acosf(rho);
        const float s     = sqrtf(fmaxf(1.0f - rho * rho, 0.0f));
        const float tpart = P.coef * PIf - P.one_m * theta;
        r.x = sxy * P.inv2pi * (P.one_m * s + rho * tpart);
        r.y = tpart * P.inv2pi * kv.y;
    }
    return r;
}

__global__ __launch_bounds__(256, 8) void fused_arc_conv_kernel(
    const float* __restrict__ k,
    const float* __restrict__ leak,
    const float* __restrict__ alpha,
    const float* __restrict__ beta,
    float* __restrict__ out)
{
    const int row = blockIdx.x;          // 0 .. B*B*N-1, layout (i,j,n)
    const int n   = row & (NN - 1);
    const int ij  = row >> 7;
    const int j   = ij & (BB - 1);
    const int i   = ij >> 3;

    const float a  = fmaxf(leak[0], 0.0f);
    const float w0 = fmaxf(alpha[0], 0.0f);
    const float w1 = fmaxf(alpha[1], 0.0f);
    const float w2 = fmaxf(alpha[2], 0.0f);
    const float bv = fmaxf(beta[0], 0.0f);

    const float PIf = 3.14159265358979323846f;
    Params P;
    P.one_m  = (1.0f - a) * (1.0f - a);
    P.coef   = 1.0f + a * a;
    P.inv2pi = 1.0f / (2.0f * PIf);
    P.fast   = (P.one_m == 0.0f);        // leak == 1 -> halfcoef == 1
    const float RL  = 1.0f - 1e-6f;
    const float EPS = 1e-12f;

    const float2* __restrict__ krow = reinterpret_cast<const float2*>(k) + (size_t)row * TT;
    float2* __restrict__ orow       = reinterpret_cast<float2*>(out)     + (size_t)row * TT;
    const float* __restrict__ sx = g_stdv + i * VPAD;       // std_x[t] (packed, L2-resident)
    const float* __restrict__ sy = g_stdv + j * VPAD + n;   // std_y[t] = stdv_pad[j, n+t]

    const int tid  = threadIdx.x;
    const int lane = tid & 31;
    const unsigned FULL = 0xffffffffu;

    // ---------- fully barrier-free: each iter is load -> pointwise -> shfl halo -> conv -> store
    #pragma unroll
    for (int it = 0; it < ITERS; ++it) {
        const int p = it * 512 + tid * 2;                 // even
        const float4 kv4 = *reinterpret_cast<const float4*>(krow + p); // (gp0,ntk0,gp1,ntk1)
        const float2 sxv = *reinterpret_cast<const float2*>(sx + p);   // aligned (p even)
        const float  sy0 = sy[p];
        const float  sy1 = sy[p + 1];

        const float sxy0 = sxv.x * sy0;
        const float sxy1 = sxv.y * sy1;

        float c0a, c0b, da, db;
        if (P.fast) {
            const float l0 = RL * sxy0;
            const float l1 = RL * sxy1;
            c0a = fminf(fmaxf(kv4.x, -l0), l0);  da = kv4.y;
            c0b = fminf(fmaxf(kv4.z, -l1), l1);  db = kv4.w;
        } else {
            const float dn0 = fmaxf(sxy0, EPS);
            float rho0 = fminf(fmaxf(kv4.x / dn0, -RL), RL);
            const float th0 = acosf(rho0);
            const float sn0 = sqrtf(fmaxf(1.0f - rho0 * rho0, 0.0f));
            const float tp0 = P.coef * PIf - P.one_m * th0;
            c0a = sxy0 * P.inv2pi * (P.one_m * sn0 + rho0 * tp0);
            da  = tp0 * P.inv2pi * kv4.y;

            const float dn1 = fmaxf(sxy1, EPS);
            float rho1 = fminf(fmaxf(kv4.z / dn1, -RL), RL);
            const float th1 = acosf(rho1);
            const float sn1 = sqrtf(fmaxf(1.0f - rho1 * rho1, 0.0f));
            const float tp1 = P.coef * PIf - P.one_m * th1;
            c0b = sxy1 * P.inv2pi * (P.one_m * sn1 + rho1 * tp1);
            db  = tp1 * P.inv2pi * kv4.w;
        }

        // halos via intra-warp shuffles
        float Lc = __shfl_up_sync(FULL, c0b, 1);    // point p-1 c0
        float Ld = __shfl_up_sync(FULL, db, 1);     // point p-1 d
        float Rc = __shfl_down_sync(FULL, c0a, 1);  // point p+2 c0
        float Rd = __shfl_down_sync(FULL, da, 1);   // point p+2 d

        // warp-boundary lanes recompute their single halo point (no barrier, no smem)
        if (lane == 0) {
            float2 v = make_float2(0.0f, 0.0f);
            if (p > 0) v = point_cd(krow, sx, sy, p - 1, P);
            Lc = v.x; Ld = v.y;
        }
        if (lane == 31) {
            float2 v = make_float2(0.0f, 0.0f);
            if (p + 2 < TT) v = point_cd(krow, sx, sy, p + 2, P);
            Rc = v.x; Rd = v.y;
        }

        const float kg0 = w0 * Lc  + w1 * c0a + w2 * c0b + bv;
        const float kg1 = w0 * c0a + w1 * c0b + w2 * Rc  + bv;
        const float kn0 = w0 * Ld  + w1 * da  + w2 * db  + kg0;
        const float kn1 = w0 * da  + w1 * db  + w2 * Rd  + kg1;

        __stcs(reinterpret_cast<float4*>(orow + p),
               make_float4(kg0, kn0, kg1, kn1));
    }
}

extern "C" void kernel_launch(void* const* d_in, const int* in_sizes, int n_in,
                              void* d_out, int out_size) {
    const float* k     = (const float*)d_in[0];
    const float* leak  = (const float*)d_in[1];
    const float* alpha = (const float*)d_in[2];
    const float* beta  = (const float*)d_in[3];
    float* out = (float*)d_out;

    prep_std_kernel<<<(BB * VPAD + 255) / 256, 256>>>(k);
    fused_arc_conv_kernel<<<BB * BB * NN, 256>>>(k, leak, alpha, beta, out);
}